// round 8
// baseline (speedup 1.0000x reference)
#include <cuda_runtime.h>

#define N_NODES 50000
#define N_EDGES 800000
#define IN_DIM 128
#define OUT_DIM 64
#define SCAN_BLOCKS 49        // 49 * 1024 = 50176 >= 50000
#define CSR_CAP 1000000       // N_EDGES + 4*N_NODES padding headroom

// ---------------- scratch (no allocations allowed) ----------------
__device__ float    g_Wh[N_NODES * OUT_DIM];   // projected features
__device__ float    g_adst[N_NODES];           // Wh . A_w[:64]
__device__ float    g_asrc[N_NODES];           // Wh . A_w[64:]
__device__ int      g_off[N_NODES + 1];        // padded CSR offsets (by dst)
__device__ int      g_cursor[N_NODES];         // histogram counts -> fill cursors
__device__ int      g_srcs[CSR_CAP];           // src ids grouped by dst (padded)
__device__ float    g_w[CSR_CAP];              // exp weights (padded, pads = 0)
__device__ int      g_bsum[SCAN_BLOCKS];       // per-block scan totals
__device__ int      g_bbase[SCAN_BLOCKS];      // per-block scan bases
__device__ unsigned g_maxd, g_maxs;            // global max of adst/asrc (sortable)

__device__ __forceinline__ unsigned f2sort(float f) {
    unsigned b = __float_as_uint(f);
    return (b & 0x80000000u) ? ~b : (b | 0x80000000u);
}
__device__ __forceinline__ float sort2f(unsigned u) {
    return __uint_as_float((u & 0x80000000u) ? (u & 0x7fffffffu) : ~u);
}

// ---------------- kernel 0: zero histogram + weights + init maxes ---------
__global__ void k_zero() {
    int i = blockIdx.x * blockDim.x + threadIdx.x;
    int stride = gridDim.x * blockDim.x;
    for (int j = i; j < CSR_CAP / 4; j += stride)
        reinterpret_cast<float4*>(g_w)[j] = make_float4(0.f, 0.f, 0.f, 0.f);
    for (int j = i; j < N_NODES; j += stride) g_cursor[j] = 0;
    if (i == 0) { g_maxd = 0x007FFFFFu; g_maxs = 0x007FFFFFu; }
}

// ---------------- kernel 1: histogram of dst ----------------
__global__ void k_hist(const int* __restrict__ dst) {
    int e = blockIdx.x * blockDim.x + threadIdx.x;
    if (e < N_EDGES) atomicAdd(&g_cursor[dst[e]], 1);
}

// ---------------- kernel 2: Wh = h@W + b, attention partials, global max --
__global__ __launch_bounds__(256) void k_gemm(
    const float* __restrict__ h, const float* __restrict__ Ww,
    const float* __restrict__ Wb, const float* __restrict__ Aw)
{
    __shared__ float sh_h[64][65];
    __shared__ float sW[64][64];

    const int tid = threadIdx.x;
    const int cg  = tid & 7;
    const int r0  = tid >> 3;
    const int row0 = blockIdx.x * 64;

    float acc[2][8];
#pragma unroll
    for (int r = 0; r < 2; r++)
#pragma unroll
        for (int j = 0; j < 8; j++) acc[r][j] = 0.f;

    for (int kc = 0; kc < IN_DIM; kc += 64) {
        __syncthreads();
#pragma unroll
        for (int p = 0; p < 4; p++) {
            int idx = p * 256 + tid;
            int row = idx >> 4;
            int c4  = idx & 15;
            int gr  = row0 + row;
            float4 v = make_float4(0.f, 0.f, 0.f, 0.f);
            if (gr < N_NODES)
                v = *reinterpret_cast<const float4*>(&h[gr * IN_DIM + kc + c4 * 4]);
            sh_h[row][c4 * 4 + 0] = v.x;
            sh_h[row][c4 * 4 + 1] = v.y;
            sh_h[row][c4 * 4 + 2] = v.z;
            sh_h[row][c4 * 4 + 3] = v.w;
        }
#pragma unroll
        for (int p = 0; p < 4; p++) {
            int idx = p * 256 + tid;
            int k  = idx >> 4;
            int c4 = idx & 15;
            float4 v = *reinterpret_cast<const float4*>(&Ww[(kc + k) * OUT_DIM + c4 * 4]);
            *reinterpret_cast<float4*>(&sW[k][c4 * 4]) = v;
        }
        __syncthreads();

#pragma unroll
        for (int k = 0; k < 64; k++) {
            float a0 = sh_h[r0][k];
            float a1 = sh_h[r0 + 32][k];
            float4 w0 = *reinterpret_cast<const float4*>(&sW[k][cg * 8]);
            float4 w1 = *reinterpret_cast<const float4*>(&sW[k][cg * 8 + 4]);
            acc[0][0] += a0 * w0.x; acc[0][1] += a0 * w0.y;
            acc[0][2] += a0 * w0.z; acc[0][3] += a0 * w0.w;
            acc[0][4] += a0 * w1.x; acc[0][5] += a0 * w1.y;
            acc[0][6] += a0 * w1.z; acc[0][7] += a0 * w1.w;
            acc[1][0] += a1 * w0.x; acc[1][1] += a1 * w0.y;
            acc[1][2] += a1 * w0.z; acc[1][3] += a1 * w0.w;
            acc[1][4] += a1 * w1.x; acc[1][5] += a1 * w1.y;
            acc[1][6] += a1 * w1.z; acc[1][7] += a1 * w1.w;
        }
    }

#pragma unroll
    for (int j = 0; j < 8; j++) {
        float b = Wb[cg * 8 + j];
        acc[0][j] += b;
        acc[1][j] += b;
    }

    float pd[2] = {0.f, 0.f}, ps[2] = {0.f, 0.f};
#pragma unroll
    for (int j = 0; j < 8; j++) {
        float a1v = Aw[cg * 8 + j];
        float a2v = Aw[OUT_DIM + cg * 8 + j];
        pd[0] += acc[0][j] * a1v; ps[0] += acc[0][j] * a2v;
        pd[1] += acc[1][j] * a1v; ps[1] += acc[1][j] * a2v;
    }
#pragma unroll
    for (int off = 1; off < 8; off <<= 1) {
        pd[0] += __shfl_xor_sync(0xffffffffu, pd[0], off);
        ps[0] += __shfl_xor_sync(0xffffffffu, ps[0], off);
        pd[1] += __shfl_xor_sync(0xffffffffu, pd[1], off);
        ps[1] += __shfl_xor_sync(0xffffffffu, ps[1], off);
    }

#pragma unroll
    for (int r = 0; r < 2; r++) {
        int gr = row0 + r0 + r * 32;
        if (gr < N_NODES) {
            float4 o0 = make_float4(acc[r][0], acc[r][1], acc[r][2], acc[r][3]);
            float4 o1 = make_float4(acc[r][4], acc[r][5], acc[r][6], acc[r][7]);
            *reinterpret_cast<float4*>(&g_Wh[gr * OUT_DIM + cg * 8])     = o0;
            *reinterpret_cast<float4*>(&g_Wh[gr * OUT_DIM + cg * 8 + 4]) = o1;
            if (cg == 0) {
                g_adst[gr] = pd[r];
                g_asrc[gr] = ps[r];
                atomicMax(&g_maxd, f2sort(pd[r]));
                atomicMax(&g_maxs, f2sort(ps[r]));
            }
        }
    }
}

// ---------------- scan A: per-block exclusive scan of PADDED degrees ------
__global__ __launch_bounds__(1024) void k_scanA() {
    __shared__ int wsum[32];
    int gid  = blockIdx.x * 1024 + threadIdx.x;
    int lane = threadIdx.x & 31;
    int wid  = threadIdx.x >> 5;

    int deg = (gid < N_NODES) ? g_cursor[gid] : 0;
    int v = (deg + 3) & ~3;            // pad to multiple of 4
    int x = v;
#pragma unroll
    for (int o = 1; o < 32; o <<= 1) {
        int t = __shfl_up_sync(0xffffffffu, x, o);
        if (lane >= o) x += t;
    }
    if (lane == 31) wsum[wid] = x;
    __syncthreads();
    if (wid == 0) {
        int y = wsum[lane];
#pragma unroll
        for (int o = 1; o < 32; o <<= 1) {
            int t = __shfl_up_sync(0xffffffffu, y, o);
            if (lane >= o) y += t;
        }
        wsum[lane] = y;
    }
    __syncthreads();
    int base = (wid > 0) ? wsum[wid - 1] : 0;
    if (gid < N_NODES) g_off[gid] = base + x - v;   // block-local exclusive
    if (threadIdx.x == 1023) g_bsum[blockIdx.x] = base + x;
}

// ---------------- scan B: exclusive scan of block totals ------------------
__global__ void k_scanB() {
    if (threadIdx.x == 0) {
        int run = 0;
        for (int i = 0; i < SCAN_BLOCKS; i++) {
            int v = g_bsum[i];
            g_bbase[i] = run;
            run += v;
        }
        g_off[N_NODES] = run;        // total padded length
    }
}

// ---------------- scan C: add block bases, set cursors --------------------
__global__ __launch_bounds__(1024) void k_scanC() {
    int gid = blockIdx.x * 1024 + threadIdx.x;
    int b = g_bbase[blockIdx.x];
    if (gid < N_NODES) {
        int o = g_off[gid] + b;
        g_off[gid] = o;
        g_cursor[gid] = o;
    }
}

// ---------------- fill CSR + fused edge-weight computation ----------------
__global__ void k_fill(const int* __restrict__ src, const int* __restrict__ dst,
                       const float* __restrict__ Ab) {
    int e = blockIdx.x * blockDim.x + threadIdx.x;
    if (e >= N_EDGES) return;
    int s = src[e], d = dst[e];
    int pos = atomicAdd(&g_cursor[d], 1);

    float ab = Ab[0];
    float xb = sort2f(g_maxd) + sort2f(g_maxs) + ab;   // global stabilizer
    float M  = xb > 0.f ? xb : 0.2f * xb;
    float x  = __ldg(&g_adst[d]) + __ldg(&g_asrc[s]) + ab;
    x = (x > 0.f ? x : 0.2f * x) - M;

    g_srcs[pos] = s;
    g_w[pos]    = __expf(x);
}

// ---------------- gather: normalize + weighted aggregate ------------------
// One warp per dst node. Padded segments -> float4/int4 loads, no tails.
__global__ __launch_bounds__(256) void k_gather(float2* __restrict__ out2)
{
    int warp = (blockIdx.x * 256 + threadIdx.x) >> 5;
    int lane = threadIdx.x & 31;
    if (warp >= N_NODES) return;

    int off0 = g_off[warp];
    int off1 = g_off[warp + 1];

    const float2* __restrict__ Wh2 = reinterpret_cast<const float2*>(g_Wh);
    const float4* __restrict__ w4p = reinterpret_cast<const float4*>(g_w);
    const int4*   __restrict__ s4p = reinterpret_cast<const int4*>(g_srcs);

    float2 acc = make_float2(0.f, 0.f);
    float den = 0.f;

    int q  = off0 >> 2;        // quad index (16B aligned, padded)
    int qe = off1 >> 2;

    // two quads per iteration (8 edges in flight)
    for (; q + 2 <= qe; q += 2) {
        float4 w0 = __ldg(&w4p[q]);
        float4 w1 = __ldg(&w4p[q + 1]);
        int4   s0 = __ldg(&s4p[q]);
        int4   s1 = __ldg(&s4p[q + 1]);
        float2 v0 = Wh2[s0.x * 32 + lane];
        float2 v1 = Wh2[s0.y * 32 + lane];
        float2 v2 = Wh2[s0.z * 32 + lane];
        float2 v3 = Wh2[s0.w * 32 + lane];
        float2 v4 = Wh2[s1.x * 32 + lane];
        float2 v5 = Wh2[s1.y * 32 + lane];
        float2 v6 = Wh2[s1.z * 32 + lane];
        float2 v7 = Wh2[s1.w * 32 + lane];
        acc.x += w0.x * v0.x; acc.y += w0.x * v0.y;
        acc.x += w0.y * v1.x; acc.y += w0.y * v1.y;
        acc.x += w0.z * v2.x; acc.y += w0.z * v2.y;
        acc.x += w0.w * v3.x; acc.y += w0.w * v3.y;
        acc.x += w1.x * v4.x; acc.y += w1.x * v4.y;
        acc.x += w1.y * v5.x; acc.y += w1.y * v5.y;
        acc.x += w1.z * v6.x; acc.y += w1.z * v6.y;
        acc.x += w1.w * v7.x; acc.y += w1.w * v7.y;
        den += (w0.x + w0.y) + (w0.z + w0.w) + (w1.x + w1.y) + (w1.z + w1.w);
    }
    if (q < qe) {              // remainder is exactly one quad
        float4 w0 = __ldg(&w4p[q]);
        int4   s0 = __ldg(&s4p[q]);
        float2 v0 = Wh2[s0.x * 32 + lane];
        float2 v1 = Wh2[s0.y * 32 + lane];
        float2 v2 = Wh2[s0.z * 32 + lane];
        float2 v3 = Wh2[s0.w * 32 + lane];
        acc.x += w0.x * v0.x; acc.y += w0.x * v0.y;
        acc.x += w0.y * v1.x; acc.y += w0.y * v1.y;
        acc.x += w0.z * v2.x; acc.y += w0.z * v2.y;
        acc.x += w0.w * v3.x; acc.y += w0.w * v3.y;
        den += (w0.x + w0.y) + (w0.z + w0.w);
    }

    float inv = (off1 > off0) ? 1.f / den : 0.f;   // isolated node -> zeros
    out2[warp * 32 + lane] = make_float2(acc.x * inv, acc.y * inv);
}

// ---------------- launch ----------------
extern "C" void kernel_launch(void* const* d_in, const int* in_sizes, int n_in,
                              void* d_out, int out_size) {
    const float* h   = (const float*)d_in[0];
    const float* Ww  = (const float*)d_in[1];
    const float* Wb  = (const float*)d_in[2];
    const float* Aw  = (const float*)d_in[3];
    const float* Ab  = (const float*)d_in[4];
    const int*   src = (const int*)d_in[5];
    const int*   dst = (const int*)d_in[6];
    float2* out2 = (float2*)d_out;

    k_zero<<<1024, 256>>>();
    k_hist<<<(N_EDGES + 255) / 256, 256>>>(dst);
    k_gemm<<<(N_NODES + 63) / 64, 256>>>(h, Ww, Wb, Aw);
    k_scanA<<<SCAN_BLOCKS, 1024>>>();
    k_scanB<<<1, 32>>>();
    k_scanC<<<SCAN_BLOCKS, 1024>>>();
    k_fill<<<(N_EDGES + 255) / 256, 256>>>(src, dst, Ab);
    k_gather<<<(N_NODES * 32 + 255) / 256, 256>>>(out2);
}

// round 9
// speedup vs baseline: 1.1315x; 1.1315x over previous
#include <cuda_runtime.h>

#define N_NODES 50000
#define N_EDGES 800000
#define IN_DIM 128
#define OUT_DIM 64
#define SCAN_BLOCKS 49        // 49 * 1024 = 50176 >= 50000
#define GEMM_BLOCKS ((N_NODES + 63) / 64)          // 782
#define HIST_BLOCKS ((N_EDGES + 255) / 256)        // 3125

// ---------------- scratch (no allocations allowed) ----------------
__device__ float    g_Wh[N_NODES * OUT_DIM];   // projected features
__device__ float    g_adst[N_NODES];           // Wh . A_w[:64]
__device__ float    g_asrc[N_NODES];           // Wh . A_w[64:]
__device__ int      g_off[N_NODES + 1];        // CSR offsets (by dst)
__device__ int      g_cursor[N_NODES];         // histogram counts -> fill cursors
__device__ int      g_srcs[N_EDGES];           // src ids grouped by dst
__device__ float    g_w[N_EDGES];              // exp weights grouped by dst
__device__ int      g_bsum[SCAN_BLOCKS];       // per-block scan totals
__device__ unsigned g_maxd, g_maxs;            // global max of adst/asrc (sortable)

__device__ __forceinline__ unsigned f2sort(float f) {
    unsigned b = __float_as_uint(f);
    return (b & 0x80000000u) ? ~b : (b | 0x80000000u);
}
__device__ __forceinline__ float sort2f(unsigned u) {
    return __uint_as_float((u & 0x80000000u) ? (u & 0x7fffffffu) : ~u);
}

// ---------------- kernel 0: zero histogram + init maxes ----------------
__global__ void k_zero() {
    int i = blockIdx.x * blockDim.x + threadIdx.x;
    if (i < N_NODES) g_cursor[i] = 0;
    if (i == 0) { g_maxd = 0x007FFFFFu; g_maxs = 0x007FFFFFu; }
}

// ------- kernel 1: dual-role grid: GEMM blocks + histogram blocks ---------
// blocks [0, GEMM_BLOCKS): Wh = h@W + b, attention partials, global maxes
// blocks [GEMM_BLOCKS, +HIST_BLOCKS): histogram of dst into g_cursor
__global__ __launch_bounds__(256) void k_gemm_hist(
    const float* __restrict__ h, const float* __restrict__ Ww,
    const float* __restrict__ Wb, const float* __restrict__ Aw,
    const int* __restrict__ dst)
{
    if (blockIdx.x >= GEMM_BLOCKS) {
        // ---- histogram role ----
        int e = (blockIdx.x - GEMM_BLOCKS) * 256 + threadIdx.x;
        if (e < N_EDGES) atomicAdd(&g_cursor[dst[e]], 1);
        return;
    }

    // ---- GEMM role ----
    __shared__ float sh_h[64][65];
    __shared__ float sW[64][64];

    const int tid = threadIdx.x;
    const int cg  = tid & 7;
    const int r0  = tid >> 3;
    const int row0 = blockIdx.x * 64;

    float acc[2][8];
#pragma unroll
    for (int r = 0; r < 2; r++)
#pragma unroll
        for (int j = 0; j < 8; j++) acc[r][j] = 0.f;

    for (int kc = 0; kc < IN_DIM; kc += 64) {
        __syncthreads();
#pragma unroll
        for (int p = 0; p < 4; p++) {
            int idx = p * 256 + tid;
            int row = idx >> 4;
            int c4  = idx & 15;
            int gr  = row0 + row;
            float4 v = make_float4(0.f, 0.f, 0.f, 0.f);
            if (gr < N_NODES)
                v = *reinterpret_cast<const float4*>(&h[gr * IN_DIM + kc + c4 * 4]);
            sh_h[row][c4 * 4 + 0] = v.x;
            sh_h[row][c4 * 4 + 1] = v.y;
            sh_h[row][c4 * 4 + 2] = v.z;
            sh_h[row][c4 * 4 + 3] = v.w;
        }
#pragma unroll
        for (int p = 0; p < 4; p++) {
            int idx = p * 256 + tid;
            int k  = idx >> 4;
            int c4 = idx & 15;
            float4 v = *reinterpret_cast<const float4*>(&Ww[(kc + k) * OUT_DIM + c4 * 4]);
            *reinterpret_cast<float4*>(&sW[k][c4 * 4]) = v;
        }
        __syncthreads();

#pragma unroll
        for (int k = 0; k < 64; k++) {
            float a0 = sh_h[r0][k];
            float a1 = sh_h[r0 + 32][k];
            float4 w0 = *reinterpret_cast<const float4*>(&sW[k][cg * 8]);
            float4 w1 = *reinterpret_cast<const float4*>(&sW[k][cg * 8 + 4]);
            acc[0][0] += a0 * w0.x; acc[0][1] += a0 * w0.y;
            acc[0][2] += a0 * w0.z; acc[0][3] += a0 * w0.w;
            acc[0][4] += a0 * w1.x; acc[0][5] += a0 * w1.y;
            acc[0][6] += a0 * w1.z; acc[0][7] += a0 * w1.w;
            acc[1][0] += a1 * w0.x; acc[1][1] += a1 * w0.y;
            acc[1][2] += a1 * w0.z; acc[1][3] += a1 * w0.w;
            acc[1][4] += a1 * w1.x; acc[1][5] += a1 * w1.y;
            acc[1][6] += a1 * w1.z; acc[1][7] += a1 * w1.w;
        }
    }

#pragma unroll
    for (int j = 0; j < 8; j++) {
        float b = Wb[cg * 8 + j];
        acc[0][j] += b;
        acc[1][j] += b;
    }

    float pd[2] = {0.f, 0.f}, ps[2] = {0.f, 0.f};
#pragma unroll
    for (int j = 0; j < 8; j++) {
        float a1v = Aw[cg * 8 + j];
        float a2v = Aw[OUT_DIM + cg * 8 + j];
        pd[0] += acc[0][j] * a1v; ps[0] += acc[0][j] * a2v;
        pd[1] += acc[1][j] * a1v; ps[1] += acc[1][j] * a2v;
    }
#pragma unroll
    for (int off = 1; off < 8; off <<= 1) {
        pd[0] += __shfl_xor_sync(0xffffffffu, pd[0], off);
        ps[0] += __shfl_xor_sync(0xffffffffu, ps[0], off);
        pd[1] += __shfl_xor_sync(0xffffffffu, pd[1], off);
        ps[1] += __shfl_xor_sync(0xffffffffu, ps[1], off);
    }

#pragma unroll
    for (int r = 0; r < 2; r++) {
        int gr = row0 + r0 + r * 32;
        if (gr < N_NODES) {
            float4 o0 = make_float4(acc[r][0], acc[r][1], acc[r][2], acc[r][3]);
            float4 o1 = make_float4(acc[r][4], acc[r][5], acc[r][6], acc[r][7]);
            *reinterpret_cast<float4*>(&g_Wh[gr * OUT_DIM + cg * 8])     = o0;
            *reinterpret_cast<float4*>(&g_Wh[gr * OUT_DIM + cg * 8 + 4]) = o1;
            if (cg == 0) {
                g_adst[gr] = pd[r];
                g_asrc[gr] = ps[r];
                atomicMax(&g_maxd, f2sort(pd[r]));
                atomicMax(&g_maxs, f2sort(ps[r]));
            }
        }
    }
}

// ---------------- scan A: per-block exclusive scan + block totals ---------
__global__ __launch_bounds__(1024) void k_scanA() {
    __shared__ int wsum[32];
    int gid  = blockIdx.x * 1024 + threadIdx.x;
    int lane = threadIdx.x & 31;
    int wid  = threadIdx.x >> 5;

    int v = (gid < N_NODES) ? g_cursor[gid] : 0;
    int x = v;
#pragma unroll
    for (int o = 1; o < 32; o <<= 1) {
        int t = __shfl_up_sync(0xffffffffu, x, o);
        if (lane >= o) x += t;
    }
    if (lane == 31) wsum[wid] = x;
    __syncthreads();
    if (wid == 0) {
        int y = wsum[lane];
#pragma unroll
        for (int o = 1; o < 32; o <<= 1) {
            int t = __shfl_up_sync(0xffffffffu, y, o);
            if (lane >= o) y += t;
        }
        wsum[lane] = y;
    }
    __syncthreads();
    int base = (wid > 0) ? wsum[wid - 1] : 0;
    if (gid < N_NODES) g_off[gid] = base + x - v;   // block-local exclusive
    if (threadIdx.x == 1023) g_bsum[blockIdx.x] = base + x;
}

// -------- scan C: lookback over block totals + add base + set cursors -----
__global__ __launch_bounds__(1024) void k_scanC() {
    __shared__ int sbase;
    int b = blockIdx.x;
    if (threadIdx.x < 32) {
        int sum = 0;
        for (int i = threadIdx.x; i < b; i += 32) sum += g_bsum[i];
#pragma unroll
        for (int o = 16; o; o >>= 1) sum += __shfl_xor_sync(0xffffffffu, sum, o);
        if (threadIdx.x == 0) sbase = sum;
    }
    __syncthreads();
    int gid = b * 1024 + threadIdx.x;
    if (gid < N_NODES) {
        int o = g_off[gid] + sbase;
        g_off[gid] = o;
        g_cursor[gid] = o;
    }
    if (gid == 0) g_off[N_NODES] = N_EDGES;
}

// ---------------- fill CSR + fused edge-weight computation ----------------
__global__ void k_fill(const int* __restrict__ src, const int* __restrict__ dst,
                       const float* __restrict__ Ab) {
    int e = blockIdx.x * blockDim.x + threadIdx.x;
    if (e >= N_EDGES) return;
    int s = src[e], d = dst[e];
    int pos = atomicAdd(&g_cursor[d], 1);

    float ab = Ab[0];
    float xb = sort2f(g_maxd) + sort2f(g_maxs) + ab;   // global stabilizer
    float M  = xb > 0.f ? xb : 0.2f * xb;
    float x  = __ldg(&g_adst[d]) + __ldg(&g_asrc[s]) + ab;
    x = (x > 0.f ? x : 0.2f * x) - M;

    g_srcs[pos] = s;
    g_w[pos]    = __expf(x);
}

// ---------------- gather: normalize + weighted aggregate ------------------
// One warp per dst node. Weights precomputed -> no shuffles, high MLP.
__global__ __launch_bounds__(256) void k_gather(float2* __restrict__ out2)
{
    int warp = (blockIdx.x * 256 + threadIdx.x) >> 5;
    int lane = threadIdx.x & 31;
    if (warp >= N_NODES) return;

    int off0 = g_off[warp];
    int off1 = g_off[warp + 1];

    const float2* __restrict__ Wh2 = reinterpret_cast<const float2*>(g_Wh);
    float2 acc = make_float2(0.f, 0.f);
    float den = 0.f;

    int j = off0;
    for (; j + 4 <= off1; j += 4) {
        float w0 = __ldg(&g_w[j]);
        float w1 = __ldg(&g_w[j + 1]);
        float w2 = __ldg(&g_w[j + 2]);
        float w3 = __ldg(&g_w[j + 3]);
        int s0 = __ldg(&g_srcs[j]);
        int s1 = __ldg(&g_srcs[j + 1]);
        int s2 = __ldg(&g_srcs[j + 2]);
        int s3 = __ldg(&g_srcs[j + 3]);
        float2 v0 = Wh2[s0 * 32 + lane];
        float2 v1 = Wh2[s1 * 32 + lane];
        float2 v2 = Wh2[s2 * 32 + lane];
        float2 v3 = Wh2[s3 * 32 + lane];
        acc.x += w0 * v0.x; acc.y += w0 * v0.y;
        acc.x += w1 * v1.x; acc.y += w1 * v1.y;
        acc.x += w2 * v2.x; acc.y += w2 * v2.y;
        acc.x += w3 * v3.x; acc.y += w3 * v3.y;
        den += w0 + w1 + w2 + w3;
    }
    for (; j < off1; j++) {
        float w = __ldg(&g_w[j]);
        int   s = __ldg(&g_srcs[j]);
        float2 v = Wh2[s * 32 + lane];
        acc.x += w * v.x;
        acc.y += w * v.y;
        den += w;
    }

    float inv = (off1 > off0) ? 1.f / den : 0.f;   // isolated node -> zeros
    out2[warp * 32 + lane] = make_float2(acc.x * inv, acc.y * inv);
}

// ---------------- launch ----------------
extern "C" void kernel_launch(void* const* d_in, const int* in_sizes, int n_in,
                              void* d_out, int out_size) {
    const float* h   = (const float*)d_in[0];
    const float* Ww  = (const float*)d_in[1];
    const float* Wb  = (const float*)d_in[2];
    const float* Aw  = (const float*)d_in[3];
    const float* Ab  = (const float*)d_in[4];
    const int*   src = (const int*)d_in[5];
    const int*   dst = (const int*)d_in[6];
    float2* out2 = (float2*)d_out;

    k_zero<<<(N_NODES + 255) / 256, 256>>>();
    k_gemm_hist<<<GEMM_BLOCKS + HIST_BLOCKS, 256>>>(h, Ww, Wb, Aw, dst);
    k_scanA<<<SCAN_BLOCKS, 1024>>>();
    k_scanC<<<SCAN_BLOCKS, 1024>>>();
    k_fill<<<(N_EDGES + 255) / 256, 256>>>(src, dst, Ab);
    k_gather<<<(N_NODES * 32 + 255) / 256, 256>>>(out2);
}

// round 10
// speedup vs baseline: 1.1688x; 1.0330x over previous
#include <cuda_runtime.h>

#define N_NODES 50000
#define N_EDGES 800000
#define IN_DIM 128
#define OUT_DIM 64
#define SCAN_BLOCKS 49        // 49 * 1024 = 50176 >= 50000
#define GEMM_BLOCKS ((N_NODES + 63) / 64)          // 782
#define HIST_BLOCKS ((N_EDGES + 255) / 256)        // 3125

// ---------------- scratch (no allocations allowed) ----------------
__device__ float    g_Wh[N_NODES * OUT_DIM];   // projected features
__device__ float    g_adst[N_NODES];           // Wh . A_w[:64]
__device__ float    g_asrc[N_NODES];           // Wh . A_w[64:]
__device__ int      g_off[N_NODES + 1];        // CSR offsets (by dst)
__device__ int      g_cursor[N_NODES];         // histogram counts -> fill cursors
__device__ int2     g_edge[N_EDGES];           // {src id, weight bits} grouped by dst
__device__ int      g_bsum[SCAN_BLOCKS];       // per-block scan totals
__device__ int      g_flag[SCAN_BLOCKS];       // publish flags for lookback
__device__ unsigned g_maxd, g_maxs;            // global max of adst/asrc (sortable)

__device__ __forceinline__ unsigned f2sort(float f) {
    unsigned b = __float_as_uint(f);
    return (b & 0x80000000u) ? ~b : (b | 0x80000000u);
}
__device__ __forceinline__ float sort2f(unsigned u) {
    return __uint_as_float((u & 0x80000000u) ? (u & 0x7fffffffu) : ~u);
}

// ---------------- kernel 0: zero histogram + flags + init maxes -----------
__global__ void k_zero() {
    int i = blockIdx.x * blockDim.x + threadIdx.x;
    if (i < N_NODES) g_cursor[i] = 0;
    if (i < SCAN_BLOCKS) g_flag[i] = 0;
    if (i == 0) { g_maxd = 0x007FFFFFu; g_maxs = 0x007FFFFFu; }
}

// ------- kernel 1: dual-role grid: GEMM blocks + histogram blocks ---------
__global__ __launch_bounds__(256) void k_gemm_hist(
    const float* __restrict__ h, const float* __restrict__ Ww,
    const float* __restrict__ Wb, const float* __restrict__ Aw,
    const int* __restrict__ dst)
{
    if (blockIdx.x >= GEMM_BLOCKS) {
        int e = (blockIdx.x - GEMM_BLOCKS) * 256 + threadIdx.x;
        if (e < N_EDGES) atomicAdd(&g_cursor[dst[e]], 1);
        return;
    }

    __shared__ float sh_h[64][65];
    __shared__ float sW[64][64];

    const int tid = threadIdx.x;
    const int cg  = tid & 7;
    const int r0  = tid >> 3;
    const int row0 = blockIdx.x * 64;

    float acc[2][8];
#pragma unroll
    for (int r = 0; r < 2; r++)
#pragma unroll
        for (int j = 0; j < 8; j++) acc[r][j] = 0.f;

    for (int kc = 0; kc < IN_DIM; kc += 64) {
        __syncthreads();
#pragma unroll
        for (int p = 0; p < 4; p++) {
            int idx = p * 256 + tid;
            int row = idx >> 4;
            int c4  = idx & 15;
            int gr  = row0 + row;
            float4 v = make_float4(0.f, 0.f, 0.f, 0.f);
            if (gr < N_NODES)
                v = *reinterpret_cast<const float4*>(&h[gr * IN_DIM + kc + c4 * 4]);
            sh_h[row][c4 * 4 + 0] = v.x;
            sh_h[row][c4 * 4 + 1] = v.y;
            sh_h[row][c4 * 4 + 2] = v.z;
            sh_h[row][c4 * 4 + 3] = v.w;
        }
#pragma unroll
        for (int p = 0; p < 4; p++) {
            int idx = p * 256 + tid;
            int k  = idx >> 4;
            int c4 = idx & 15;
            float4 v = *reinterpret_cast<const float4*>(&Ww[(kc + k) * OUT_DIM + c4 * 4]);
            *reinterpret_cast<float4*>(&sW[k][c4 * 4]) = v;
        }
        __syncthreads();

#pragma unroll
        for (int k = 0; k < 64; k++) {
            float a0 = sh_h[r0][k];
            float a1 = sh_h[r0 + 32][k];
            float4 w0 = *reinterpret_cast<const float4*>(&sW[k][cg * 8]);
            float4 w1 = *reinterpret_cast<const float4*>(&sW[k][cg * 8 + 4]);
            acc[0][0] += a0 * w0.x; acc[0][1] += a0 * w0.y;
            acc[0][2] += a0 * w0.z; acc[0][3] += a0 * w0.w;
            acc[0][4] += a0 * w1.x; acc[0][5] += a0 * w1.y;
            acc[0][6] += a0 * w1.z; acc[0][7] += a0 * w1.w;
            acc[1][0] += a1 * w0.x; acc[1][1] += a1 * w0.y;
            acc[1][2] += a1 * w0.z; acc[1][3] += a1 * w0.w;
            acc[1][4] += a1 * w1.x; acc[1][5] += a1 * w1.y;
            acc[1][6] += a1 * w1.z; acc[1][7] += a1 * w1.w;
        }
    }

#pragma unroll
    for (int j = 0; j < 8; j++) {
        float b = Wb[cg * 8 + j];
        acc[0][j] += b;
        acc[1][j] += b;
    }

    float pd[2] = {0.f, 0.f}, ps[2] = {0.f, 0.f};
#pragma unroll
    for (int j = 0; j < 8; j++) {
        float a1v = Aw[cg * 8 + j];
        float a2v = Aw[OUT_DIM + cg * 8 + j];
        pd[0] += acc[0][j] * a1v; ps[0] += acc[0][j] * a2v;
        pd[1] += acc[1][j] * a1v; ps[1] += acc[1][j] * a2v;
    }
#pragma unroll
    for (int off = 1; off < 8; off <<= 1) {
        pd[0] += __shfl_xor_sync(0xffffffffu, pd[0], off);
        ps[0] += __shfl_xor_sync(0xffffffffu, ps[0], off);
        pd[1] += __shfl_xor_sync(0xffffffffu, pd[1], off);
        ps[1] += __shfl_xor_sync(0xffffffffu, ps[1], off);
    }

#pragma unroll
    for (int r = 0; r < 2; r++) {
        int gr = row0 + r0 + r * 32;
        if (gr < N_NODES) {
            float4 o0 = make_float4(acc[r][0], acc[r][1], acc[r][2], acc[r][3]);
            float4 o1 = make_float4(acc[r][4], acc[r][5], acc[r][6], acc[r][7]);
            *reinterpret_cast<float4*>(&g_Wh[gr * OUT_DIM + cg * 8])     = o0;
            *reinterpret_cast<float4*>(&g_Wh[gr * OUT_DIM + cg * 8 + 4]) = o1;
            if (cg == 0) {
                g_adst[gr] = pd[r];
                g_asrc[gr] = ps[r];
                atomicMax(&g_maxd, f2sort(pd[r]));
                atomicMax(&g_maxs, f2sort(ps[r]));
            }
        }
    }
}

// -------- single-kernel scan: local scan + publish + lookback -------------
// 49 blocks, all resident in wave 1 (<< 148 SMs) -> spin-wait is safe.
__global__ __launch_bounds__(1024) void k_scan() {
    __shared__ int wsum[32];
    __shared__ int sbase;
    int b    = blockIdx.x;
    int gid  = b * 1024 + threadIdx.x;
    int lane = threadIdx.x & 31;
    int wid  = threadIdx.x >> 5;

    int v = (gid < N_NODES) ? g_cursor[gid] : 0;
    int x = v;
#pragma unroll
    for (int o = 1; o < 32; o <<= 1) {
        int t = __shfl_up_sync(0xffffffffu, x, o);
        if (lane >= o) x += t;
    }
    if (lane == 31) wsum[wid] = x;
    __syncthreads();
    if (wid == 0) {
        int y = wsum[lane];
#pragma unroll
        for (int o = 1; o < 32; o <<= 1) {
            int t = __shfl_up_sync(0xffffffffu, y, o);
            if (lane >= o) y += t;
        }
        wsum[lane] = y;
    }
    __syncthreads();
    int wbase = (wid > 0) ? wsum[wid - 1] : 0;
    int local_exc = wbase + x - v;

    // publish this block's total
    if (threadIdx.x == 1023) {
        g_bsum[b] = wbase + x;
        __threadfence();
        atomicExch(&g_flag[b], 1);
    }

    // lookback: warp 0 sums totals of all preceding blocks
    if (wid == 0) {
        int sum = 0;
        for (int i = lane; i < b; i += 32) {
            while (atomicAdd(&g_flag[i], 0) == 0) { }
            sum += g_bsum[i];
        }
#pragma unroll
        for (int o = 16; o; o >>= 1) sum += __shfl_xor_sync(0xffffffffu, sum, o);
        if (lane == 0) sbase = sum;
    }
    __syncthreads();

    if (gid < N_NODES) {
        int o = local_exc + sbase;
        g_off[gid] = o;
        g_cursor[gid] = o;
    }
    if (gid == 0) g_off[N_NODES] = N_EDGES;
}

// ---------------- fill CSR + fused edge-weight computation ----------------
__global__ void k_fill(const int* __restrict__ src, const int* __restrict__ dst,
                       const float* __restrict__ Ab) {
    int e = blockIdx.x * blockDim.x + threadIdx.x;
    if (e >= N_EDGES) return;
    int s = src[e], d = dst[e];
    int pos = atomicAdd(&g_cursor[d], 1);

    float ab = Ab[0];
    float xb = sort2f(g_maxd) + sort2f(g_maxs) + ab;   // global stabilizer
    float M  = xb > 0.f ? xb : 0.2f * xb;
    float x  = __ldg(&g_adst[d]) + __ldg(&g_asrc[s]) + ab;
    x = (x > 0.f ? x : 0.2f * x) - M;

    g_edge[pos] = make_int2(s, __float_as_int(__expf(x)));   // one ST.64
}

// ---------------- gather: normalize + weighted aggregate ------------------
// One warp per dst node. int2 edge records -> LDG.64 broadcasts, high MLP.
__global__ __launch_bounds__(256) void k_gather(float2* __restrict__ out2)
{
    int warp = (blockIdx.x * 256 + threadIdx.x) >> 5;
    int lane = threadIdx.x & 31;
    if (warp >= N_NODES) return;

    int off0 = g_off[warp];
    int off1 = g_off[warp + 1];

    const float2* __restrict__ Wh2 = reinterpret_cast<const float2*>(g_Wh);
    float2 acc = make_float2(0.f, 0.f);
    float den = 0.f;

    int j = off0;
    for (; j + 4 <= off1; j += 4) {
        int2 e0 = __ldg(&g_edge[j]);
        int2 e1 = __ldg(&g_edge[j + 1]);
        int2 e2 = __ldg(&g_edge[j + 2]);
        int2 e3 = __ldg(&g_edge[j + 3]);
        float w0 = __int_as_float(e0.y);
        float w1 = __int_as_float(e1.y);
        float w2 = __int_as_float(e2.y);
        float w3 = __int_as_float(e3.y);
        float2 v0 = Wh2[e0.x * 32 + lane];
        float2 v1 = Wh2[e1.x * 32 + lane];
        float2 v2 = Wh2[e2.x * 32 + lane];
        float2 v3 = Wh2[e3.x * 32 + lane];
        acc.x += w0 * v0.x; acc.y += w0 * v0.y;
        acc.x += w1 * v1.x; acc.y += w1 * v1.y;
        acc.x += w2 * v2.x; acc.y += w2 * v2.y;
        acc.x += w3 * v3.x; acc.y += w3 * v3.y;
        den += (w0 + w1) + (w2 + w3);
    }
    for (; j < off1; j++) {
        int2 e0 = __ldg(&g_edge[j]);
        float w = __int_as_float(e0.y);
        float2 v = Wh2[e0.x * 32 + lane];
        acc.x += w * v.x;
        acc.y += w * v.y;
        den += w;
    }

    float inv = (off1 > off0) ? 1.f / den : 0.f;   // isolated node -> zeros
    out2[warp * 32 + lane] = make_float2(acc.x * inv, acc.y * inv);
}

// ---------------- launch ----------------
extern "C" void kernel_launch(void* const* d_in, const int* in_sizes, int n_in,
                              void* d_out, int out_size) {
    const float* h   = (const float*)d_in[0];
    const float* Ww  = (const float*)d_in[1];
    const float* Wb  = (const float*)d_in[2];
    const float* Aw  = (const float*)d_in[3];
    const float* Ab  = (const float*)d_in[4];
    const int*   src = (const int*)d_in[5];
    const int*   dst = (const int*)d_in[6];
    float2* out2 = (float2*)d_out;

    k_zero<<<(N_NODES + 255) / 256, 256>>>();
    k_gemm_hist<<<GEMM_BLOCKS + HIST_BLOCKS, 256>>>(h, Ww, Wb, Aw, dst);
    k_scan<<<SCAN_BLOCKS, 1024>>>();
    k_fill<<<(N_EDGES + 255) / 256, 256>>>(src, dst, Ab);
    k_gather<<<(N_NODES * 32 + 255) / 256, 256>>>(out2);
}